// round 15
// baseline (speedup 1.0000x reference)
#include <cuda_runtime.h>
#include <cuda_fp16.h>
#include <cstdint>

#define NN   4096
#define FIN  256
#define NH   4
#define DHH  64
#define NW   (NN / 32)      // 128 adj-mask words per row
#define NSPLIT 4

// ------------------------- device globals (no alloc allowed) ---------------
__device__ __half g_hTh[NH * DHH * NN];   // hT[head][d][n] fp16
__device__ float  g_ssrc[NH * NN];
__device__ float  g_E[NH * NN];           // exp(s_src)
__device__ float  g_e[NH * NN];           // exp(0.01*s_src)
__device__ __half g_t_h[NH * NN];         // s_dst (half)
__device__ __half g_F_h[NH * NN];         // exp(s_dst)
__device__ __half g_f_h[NH * NN];         // exp(0.01*s_dst)
__device__ unsigned g_adjm[NN * NW];      // adjacency bitmask
__device__ float  g_acc[NSPLIT * NH * NN * DHH];  // unnormalized partials
__device__ float  g_rsp[NSPLIT * NH * NN];        // rowsum partials

// ------------------------- helpers -----------------------------------------
__device__ __forceinline__ uint32_t smem_u32(const void* p) {
    uint32_t a;
    asm("{ .reg .u64 t; cvta.to.shared.u64 t, %1; cvt.u32.u64 %0, t; }"
        : "=r"(a) : "l"(p));
    return a;
}
__device__ __forceinline__ __half2 u2h(uint32_t u) {
    union { uint32_t u; __half2 h; } c; c.u = u; return c.h;
}
__device__ __forceinline__ uint32_t h2u(__half2 h) {
    union { uint32_t u; __half2 h; } c; c.h = h; return c.u;
}
#define LDSM4(r0, r1, r2, r3, addr) \
    asm volatile("ldmatrix.sync.aligned.m8n8.x4.shared.b16 {%0,%1,%2,%3}, [%4];" \
                 : "=r"(r0), "=r"(r1), "=r"(r2), "=r"(r3) : "r"(addr))
#define MMA_F16(c, a0, a1, a2, a3, b0, b1) \
    asm volatile("mma.sync.aligned.m16n8k16.row.col.f32.f16.f16.f32 " \
                 "{%0,%1,%2,%3}, {%4,%5,%6,%7}, {%8,%9}, {%0,%1,%2,%3};" \
                 : "+f"((c)[0]), "+f"((c)[1]), "+f"((c)[2]), "+f"((c)[3]) \
                 : "r"(a0), "r"(a1), "r"(a2), "r"(a3), "r"(b0), "r"(b1))
#define CP_ASYNC16(dst, src) \
    asm volatile("cp.async.cg.shared.global [%0], [%1], 16;" \
                 :: "r"(dst), "l"(src) : "memory")
#define CP_COMMIT() asm volatile("cp.async.commit_group;" ::: "memory")
#define CP_WAIT1()  asm volatile("cp.async.wait_group 1;" ::: "memory")

// ---------------------------------------------------------------------------
// Kernel 0: pack adj into bitmask words. Ballot-style, fully coalesced.
// ---------------------------------------------------------------------------
__global__ __launch_bounds__(256) void k0_pack(const int* __restrict__ adj) {
    const int warp_g = (blockIdx.x * 256 + threadIdx.x) >> 5;
    const int lane   = threadIdx.x & 31;
    const int* p = adj + (size_t)warp_g * 256 + lane;
    int v[8];
#pragma unroll
    for (int q = 0; q < 8; q++) v[q] = p[q * 32];
#pragma unroll
    for (int q = 0; q < 8; q++) {
        unsigned b = __ballot_sync(0xffffffffu, v[q] != 0);
        if (lane == 0) g_adjm[warp_g * 8 + q] = b;
    }
}

// ---------------------------------------------------------------------------
// Kernel 1 (fused scores): h-tile = x @ W, write fp16 hT + score tables.
// ---------------------------------------------------------------------------
__global__ __launch_bounds__(128) void k1_fused(const float* __restrict__ x,
                                                const float* __restrict__ W,
                                                const float* __restrict__ a) {
    __shared__ float xs[64][36];
    __shared__ float ws[64][68];
    __shared__ float sr1[32][17];
    __shared__ float sr2[32][17];

    const int head = blockIdx.x;
    const int n0   = blockIdx.y * 32;
    const int tid  = threadIdx.x;
    const int tx   = tid & 15;
    const int ty   = tid >> 4;
    const float* Wh = W + (size_t)head * FIN * DHH;

    float c[4][4] = {};
    for (int f0 = 0; f0 < FIN; f0 += 64) {
        __syncthreads();
#pragma unroll
        for (int r = 0; r < 4; r++) {
            int idx = tid + r * 128;
            int row = idx >> 4;
            int c4  = idx & 15;
            float4 v = *(const float4*)(x + (size_t)(n0 + row) * FIN + f0 + c4 * 4);
            xs[c4 * 4 + 0][row] = v.x;
            xs[c4 * 4 + 1][row] = v.y;
            xs[c4 * 4 + 2][row] = v.z;
            xs[c4 * 4 + 3][row] = v.w;
        }
#pragma unroll
        for (int r = 0; r < 8; r++) {
            int idx = tid + r * 128;
            int row = idx >> 4;
            int c4  = idx & 15;
            *(float4*)&ws[row][c4 * 4] =
                *(const float4*)(Wh + (size_t)(f0 + row) * DHH + c4 * 4);
        }
        __syncthreads();
#pragma unroll 16
        for (int k = 0; k < 64; k++) {
            float4 av = *(const float4*)&xs[k][ty * 4];
            float4 bv = *(const float4*)&ws[k][tx * 4];
            const float aa[4] = {av.x, av.y, av.z, av.w};
            const float bb[4] = {bv.x, bv.y, bv.z, bv.w};
#pragma unroll
            for (int ii = 0; ii < 4; ii++)
#pragma unroll
                for (int jj = 0; jj < 4; jj++)
                    c[ii][jj] = fmaf(aa[ii], bb[jj], c[ii][jj]);
        }
    }

    __half* htb = g_hTh + (size_t)head * DHH * NN + n0 + ty * 4;
#pragma unroll
    for (int jj = 0; jj < 4; jj++) {
        __half2 p0 = __floats2half2_rn(c[0][jj], c[1][jj]);
        __half2 p1 = __floats2half2_rn(c[2][jj], c[3][jj]);
        uint2 u = make_uint2(h2u(p0), h2u(p1));
        *(uint2*)(htb + (size_t)(tx * 4 + jj) * NN) = u;
    }

    const float4 a1v = *(const float4*)(a + head * 2 * DHH + tx * 4);
    const float4 a2v = *(const float4*)(a + head * 2 * DHH + DHH + tx * 4);
#pragma unroll
    for (int ii = 0; ii < 4; ii++) {
        sr1[ty * 4 + ii][tx] = c[ii][0] * a1v.x + c[ii][1] * a1v.y +
                               c[ii][2] * a1v.z + c[ii][3] * a1v.w;
        sr2[ty * 4 + ii][tx] = c[ii][0] * a2v.x + c[ii][1] * a2v.y +
                               c[ii][2] * a2v.z + c[ii][3] * a2v.w;
    }
    __syncthreads();
    if (tid < 32) {
        float s1 = 0.f, s2 = 0.f;
#pragma unroll
        for (int q = 0; q < 16; q++) { s1 += sr1[tid][q]; s2 += sr2[tid][q]; }
        const int idx = head * NN + n0 + tid;
        g_ssrc[idx] = s1;
        g_E[idx] = __expf(s1);
        g_e[idx] = __expf(0.01f * s1);
        g_t_h[idx] = __float2half_rn(s2);
        g_F_h[idx] = __float2half_rn(__expf(s2));
        g_f_h[idx] = __float2half_rn(__expf(0.01f * s2));
    }
}

// ---------------------------------------------------------------------------
// Kernel 3: masked-softmax aggregation via mma.sync fp16 (fp32 accum).
// NEW: register-direct A fragments (no sP, no STS-P, no LDSM-A).
// CTA = 128 i-rows x 1 head x 1024-j slice; 4 warps, each 32i x 64d.
// B tiles + t/F/f tables triple-buffered via cp.async; 1 barrier/tile.
// ---------------------------------------------------------------------------
#define TJ 64
#define JRANGE (NN / NSPLIT)
#define NT (JRANGE / TJ)
#define PITCH 72        // halves; 144B rows -> conflict-free ldmatrix
#define TILE_B 9216     // 64 * PITCH * 2 bytes

__global__ __launch_bounds__(128, 4) void k3_agg() {
    __shared__ __align__(16) __half sB[3][64 * PITCH];    // 27648 B
    __shared__ __align__(16) __half sT[3][192];           // t|F|f, 384 B each

    const int head  = blockIdx.x;
    const int i0    = blockIdx.y * 128;
    const int split = blockIdx.z;
    const int jbase = split * JRANGE;
    const int tid   = threadIdx.x;
    const int lane  = tid & 31;
    const int w     = tid >> 5;
    const int r     = lane >> 2;      // 0..7
    const int cq    = lane & 3;       // 0..3

    // 4 rows per thread: [mi*2+h] = w*32 + mi*16 + r + h*8
    int rowid[4];
    rowid[0] = w * 32 + r;
    rowid[1] = w * 32 + r + 8;
    rowid[2] = w * 32 + 16 + r;
    rowid[3] = w * 32 + 24 + r;

    uint32_t nsi[4], Ei[4], ei[4];
#pragma unroll
    for (int q = 0; q < 4; q++) {
        const int rg = head * NN + i0 + rowid[q];
        nsi[q] = h2u(__float2half2_rn(-g_ssrc[rg]));
        Ei[q]  = h2u(__float2half2_rn(g_E[rg]));
        ei[q]  = h2u(__float2half2_rn(g_e[rg]));
    }
    const uint32_t cap2 = h2u(__float2half2_rn(60000.f));

    const unsigned* madj = g_adjm + (jbase >> 5);
    const __half* hTh = g_hTh + (size_t)head * DHH * NN;

    // cp.async source pointers for the t/F/f tables (24 chunks of 16B)
    const __half* tabsrc = nullptr;
    if (tid < 24) {
        const int tab = tid >> 3;
        const __half* base = tab == 0 ? g_t_h : (tab == 1 ? g_F_h : g_f_h);
        tabsrc = base + head * NN + jbase + (tid & 7) * 8;
    }

    const uint32_t sBu = smem_u32(sB);
    const uint32_t sTu = smem_u32(sT);
    const uint32_t lrow = lane & 15;
    const uint32_t lcol = (lane >> 4) * 8;
    const uint32_t bBase = sBu + (lrow * PITCH + lcol) * 2;

    float c[16][4] = {};     // [mi*8 + nt][4]
    float rs[4] = {};

    // ---- preload tile 0 ----
#pragma unroll
    for (int k = 0; k < 4; k++) {
        int ch = tid + k * 128;
        int row = ch >> 3;
        int kc  = ch & 7;
        CP_ASYNC16(sBu + row * 144 + kc * 16,
                   hTh + (size_t)row * NN + jbase + kc * 8);
    }
    if (tid < 24) CP_ASYNC16(sTu + tid * 16, tabsrc);
    CP_COMMIT();

    int bcur = 0;
    for (int t = 0; t < NT; t++) {
        const int bnext = (bcur == 2) ? 0 : bcur + 1;

        // ---- prefetch tile t+1 ----
        if (t + 1 < NT) {
            const int j1 = jbase + (t + 1) * TJ;
            const uint32_t bb = sBu + bnext * TILE_B;
#pragma unroll
            for (int k = 0; k < 4; k++) {
                int ch = tid + k * 128;
                int row = ch >> 3;
                int kc  = ch & 7;
                CP_ASYNC16(bb + row * 144 + kc * 16,
                           hTh + (size_t)row * NN + j1 + kc * 8);
            }
            if (tid < 24)
                CP_ASYNC16(sTu + bnext * 384 + tid * 16, tabsrc + (t + 1) * TJ);
        }
        CP_COMMIT();

        // mask words for this tile: 4 rows x uint2 (64 bits)
        uint2 mw[4];
#pragma unroll
        for (int q = 0; q < 4; q++)
            mw[q] = *(const uint2*)(madj + (size_t)(i0 + rowid[q]) * NW + t * 2);

        CP_WAIT1();
        __syncthreads();     // tile t data (sB[bcur], sT[bcur]) visible

        // ---- compute A fragments in registers (+rowsums) ----
        const __half* Tt = sT[bcur];
        uint32_t afr[2][4][4];    // [mi][ks][a0..a3]
#pragma unroll
        for (int ks = 0; ks < 4; ks++) {
            const int j0 = ks * 16 + cq * 2;
            const uint32_t t0 = *(const uint32_t*)&Tt[j0];
            const uint32_t t8 = *(const uint32_t*)&Tt[j0 + 8];
            const uint32_t F0 = *(const uint32_t*)&Tt[64 + j0];
            const uint32_t F8 = *(const uint32_t*)&Tt[64 + j0 + 8];
            const uint32_t f0 = *(const uint32_t*)&Tt[128 + j0];
            const uint32_t f8 = *(const uint32_t*)&Tt[128 + j0 + 8];
            const int sh = cq * 2 + (ks & 1) * 16;
#pragma unroll
            for (int mi = 0; mi < 2; mi++) {
#pragma unroll
                for (int h = 0; h < 2; h++) {
                    const int q = mi * 2 + h;
                    const unsigned word = (ks >= 2) ? mw[q].y : mw[q].x;
                    // pair at j0
                    {
                        __half2 cmp = __hgt2(u2h(t0), u2h(nsi[q]));
                        __half2 hiv = __hmul2(u2h(Ei[q]), u2h(F0));
                        __half2 lov = __hmul2(u2h(ei[q]), u2h(f0));
                        __half2 v = __hfma2(cmp, __hsub2(hiv, lov), lov);
                        v = __hmin2(v, u2h(cap2));
                        unsigned bb2 = (word >> sh) & 3u;
                        unsigned mm = ((bb2 & 1u) * 0x3C00u) |
                                      ((bb2 >> 1) * 0x3C000000u);
                        v = __hmul2(v, u2h(mm));
                        float2 vf = __half22float2(v);
                        rs[q] += vf.x + vf.y;
                        afr[mi][ks][h] = h2u(v);          // a0 (h=0) / a1 (h=1)
                    }
                    // pair at j0+8
                    {
                        __half2 cmp = __hgt2(u2h(t8), u2h(nsi[q]));
                        __half2 hiv = __hmul2(u2h(Ei[q]), u2h(F8));
                        __half2 lov = __hmul2(u2h(ei[q]), u2h(f8));
                        __half2 v = __hfma2(cmp, __hsub2(hiv, lov), lov);
                        v = __hmin2(v, u2h(cap2));
                        unsigned bb2 = (word >> (sh + 8)) & 3u;
                        unsigned mm = ((bb2 & 1u) * 0x3C00u) |
                                      ((bb2 >> 1) * 0x3C000000u);
                        v = __hmul2(v, u2h(mm));
                        float2 vf = __half22float2(v);
                        rs[q] += vf.x + vf.y;
                        afr[mi][ks][2 + h] = h2u(v);      // a2 / a3
                    }
                }
            }
        }

        // ---- MMA phase: B frags transient, A from registers ----
        const uint32_t bB = bBase + bcur * TILE_B;
#pragma unroll
        for (int q2 = 0; q2 < 4; q2++) {
#pragma unroll
            for (int ks = 0; ks < 4; ks++) {
                uint32_t b0, b1, b2, b3;
                LDSM4(b0, b1, b2, b3, bB + q2 * (16 * PITCH * 2) + ks * 32);
#pragma unroll
                for (int mi = 0; mi < 2; mi++) {
                    MMA_F16(c[mi * 8 + q2 * 2 + 0],
                            afr[mi][ks][0], afr[mi][ks][1],
                            afr[mi][ks][2], afr[mi][ks][3], b0, b2);
                    MMA_F16(c[mi * 8 + q2 * 2 + 1],
                            afr[mi][ks][0], afr[mi][ks][1],
                            afr[mi][ks][2], afr[mi][ks][3], b1, b3);
                }
            }
        }
        bcur = bnext;
    }

    // ---- rowsums: reduce over the 4 lanes (cq) sharing each row ----
#pragma unroll
    for (int q = 0; q < 4; q++) {
        rs[q] += __shfl_xor_sync(0xffffffffu, rs[q], 1);
        rs[q] += __shfl_xor_sync(0xffffffffu, rs[q], 2);
    }
    if (cq == 0) {
        float* rb = g_rsp + ((size_t)split * NH + head) * NN + i0;
#pragma unroll
        for (int q = 0; q < 4; q++) rb[rowid[q]] = rs[q];
    }

    // ---- write unnormalized acc partials ----
    float* accb = g_acc + (((size_t)split * NH + head) * NN + i0) * DHH;
#pragma unroll
    for (int mi = 0; mi < 2; mi++) {
        const int row0 = rowid[mi * 2];
        const int row1 = rowid[mi * 2 + 1];
#pragma unroll
        for (int nt = 0; nt < 8; nt++) {
            const float* cf = c[mi * 8 + nt];
            const int col = nt * 8 + cq * 2;
            *(float2*)(accb + (size_t)row0 * DHH + col) =
                make_float2(cf[0], cf[1]);
            *(float2*)(accb + (size_t)row1 * DHH + col) =
                make_float2(cf[2], cf[3]);
        }
    }
}

// ---------------------------------------------------------------------------
// Kernel 4: combine 4 split partials, normalize, ELU, store (vectorized).
// ---------------------------------------------------------------------------
__global__ __launch_bounds__(256) void k4_fin(float* __restrict__ out) {
    const int g    = blockIdx.x * 256 + threadIdx.x;   // float4 index
    const int n    = g >> 6;
    const int rem  = g & 63;
    const int head = rem >> 4;
    const int d4   = rem & 15;

    float4 acc = make_float4(0.f, 0.f, 0.f, 0.f);
    float r = 0.f;
#pragma unroll
    for (int s = 0; s < NSPLIT; s++) {
        const float4 v = *(const float4*)(g_acc +
            (((size_t)s * NH + head) * NN + n) * DHH + d4 * 4);
        acc.x += v.x; acc.y += v.y; acc.z += v.z; acc.w += v.w;
        r += g_rsp[((size_t)s * NH + head) * NN + n];
    }
    const float inv = 1.0f / r;
    float z0 = acc.x * inv, z1 = acc.y * inv, z2 = acc.z * inv, z3 = acc.w * inv;
    z0 = z0 > 0.f ? z0 : expm1f(z0);
    z1 = z1 > 0.f ? z1 : expm1f(z1);
    z2 = z2 > 0.f ? z2 : expm1f(z2);
    z3 = z3 > 0.f ? z3 : expm1f(z3);
    *(float4*)(out + (size_t)g * 4) = make_float4(z0, z1, z2, z3);
}

// ---------------------------------------------------------------------------
extern "C" void kernel_launch(void* const* d_in, const int* in_sizes, int n_in,
                              void* d_out, int out_size) {
    (void)in_sizes; (void)n_in; (void)out_size;
    const float* x   = (const float*)d_in[0];
    const int*   adj = (const int*)d_in[1];
    const float* W   = (const float*)d_in[2];
    const float* a   = (const float*)d_in[3];
    float* out = (float*)d_out;

    k0_pack <<<NN * NW / (8 * 8), 256>>>(adj);
    k1_fused<<<dim3(NH, NN / 32), 128>>>(x, W, a);
    k3_agg  <<<dim3(NH, NN / 128, NSPLIT), 128>>>();
    k4_fin  <<<NN * NH * DHH / 1024, 256>>>(out);
}

// round 16
// speedup vs baseline: 1.0469x; 1.0469x over previous
#include <cuda_runtime.h>
#include <cuda_fp16.h>
#include <cstdint>

#define NN   4096
#define FIN  256
#define NH   4
#define DHH  64
#define NW   (NN / 32)      // 128 adj-mask words per row
#define NSPLIT 4

// ------------------------- device globals (no alloc allowed) ---------------
__device__ __half g_hTh[NH * DHH * NN];   // hT[head][d][n] fp16
__device__ float  g_ssrc[NH * NN];
__device__ float  g_E[NH * NN];           // exp(s_src)
__device__ float  g_e[NH * NN];           // exp(0.01*s_src)
__device__ __half g_t_h[NH * NN];         // s_dst (half)
__device__ __half g_F_h[NH * NN];         // exp(s_dst)
__device__ __half g_f_h[NH * NN];         // exp(0.01*s_dst)
__device__ unsigned g_adjm[NN * NW];      // adjacency bitmask
__device__ float  g_acc[NSPLIT * NH * NN * DHH];  // unnormalized partials
__device__ float  g_rsp[NSPLIT * NH * NN];        // rowsum partials

// ------------------------- helpers -----------------------------------------
__device__ __forceinline__ uint32_t smem_u32(const void* p) {
    uint32_t a;
    asm("{ .reg .u64 t; cvta.to.shared.u64 t, %1; cvt.u32.u64 %0, t; }"
        : "=r"(a) : "l"(p));
    return a;
}
__device__ __forceinline__ __half2 u2h(uint32_t u) {
    union { uint32_t u; __half2 h; } c; c.u = u; return c.h;
}
__device__ __forceinline__ uint32_t h2u(__half2 h) {
    union { uint32_t u; __half2 h; } c; c.h = h; return c.u;
}
#define LDSM4(r0, r1, r2, r3, addr) \
    asm volatile("ldmatrix.sync.aligned.m8n8.x4.shared.b16 {%0,%1,%2,%3}, [%4];" \
                 : "=r"(r0), "=r"(r1), "=r"(r2), "=r"(r3) : "r"(addr))
#define MMA_F16(c, a0, a1, a2, a3, b0, b1) \
    asm volatile("mma.sync.aligned.m16n8k16.row.col.f32.f16.f16.f32 " \
                 "{%0,%1,%2,%3}, {%4,%5,%6,%7}, {%8,%9}, {%0,%1,%2,%3};" \
                 : "+f"((c)[0]), "+f"((c)[1]), "+f"((c)[2]), "+f"((c)[3]) \
                 : "r"(a0), "r"(a1), "r"(a2), "r"(a3), "r"(b0), "r"(b1))
#define CP_ASYNC16(dst, src) \
    asm volatile("cp.async.cg.shared.global [%0], [%1], 16;" \
                 :: "r"(dst), "l"(src) : "memory")
#define CP_COMMIT() asm volatile("cp.async.commit_group;" ::: "memory")
#define CP_WAIT1()  asm volatile("cp.async.wait_group 1;" ::: "memory")

// ---------------------------------------------------------------------------
// Kernel 0: pack adj into bitmask words. Ballot-style, fully coalesced.
// ---------------------------------------------------------------------------
__global__ __launch_bounds__(256) void k0_pack(const int* __restrict__ adj) {
    const int warp_g = (blockIdx.x * 256 + threadIdx.x) >> 5;
    const int lane   = threadIdx.x & 31;
    const int* p = adj + (size_t)warp_g * 256 + lane;
    int v[8];
#pragma unroll
    for (int q = 0; q < 8; q++) v[q] = p[q * 32];
#pragma unroll
    for (int q = 0; q < 8; q++) {
        unsigned b = __ballot_sync(0xffffffffu, v[q] != 0);
        if (lane == 0) g_adjm[warp_g * 8 + q] = b;
    }
}

// ---------------------------------------------------------------------------
// Kernel 1 (fused scores): h-tile = x @ W, write fp16 hT + score tables.
// ---------------------------------------------------------------------------
__global__ __launch_bounds__(128) void k1_fused(const float* __restrict__ x,
                                                const float* __restrict__ W,
                                                const float* __restrict__ a) {
    __shared__ float xs[64][36];
    __shared__ float ws[64][68];
    __shared__ float sr1[32][17];
    __shared__ float sr2[32][17];

    const int head = blockIdx.x;
    const int n0   = blockIdx.y * 32;
    const int tid  = threadIdx.x;
    const int tx   = tid & 15;
    const int ty   = tid >> 4;
    const float* Wh = W + (size_t)head * FIN * DHH;

    float c[4][4] = {};
    for (int f0 = 0; f0 < FIN; f0 += 64) {
        __syncthreads();
#pragma unroll
        for (int r = 0; r < 4; r++) {
            int idx = tid + r * 128;
            int row = idx >> 4;
            int c4  = idx & 15;
            float4 v = *(const float4*)(x + (size_t)(n0 + row) * FIN + f0 + c4 * 4);
            xs[c4 * 4 + 0][row] = v.x;
            xs[c4 * 4 + 1][row] = v.y;
            xs[c4 * 4 + 2][row] = v.z;
            xs[c4 * 4 + 3][row] = v.w;
        }
#pragma unroll
        for (int r = 0; r < 8; r++) {
            int idx = tid + r * 128;
            int row = idx >> 4;
            int c4  = idx & 15;
            *(float4*)&ws[row][c4 * 4] =
                *(const float4*)(Wh + (size_t)(f0 + row) * DHH + c4 * 4);
        }
        __syncthreads();
#pragma unroll 16
        for (int k = 0; k < 64; k++) {
            float4 av = *(const float4*)&xs[k][ty * 4];
            float4 bv = *(const float4*)&ws[k][tx * 4];
            const float aa[4] = {av.x, av.y, av.z, av.w};
            const float bb[4] = {bv.x, bv.y, bv.z, bv.w};
#pragma unroll
            for (int ii = 0; ii < 4; ii++)
#pragma unroll
                for (int jj = 0; jj < 4; jj++)
                    c[ii][jj] = fmaf(aa[ii], bb[jj], c[ii][jj]);
        }
    }

    __half* htb = g_hTh + (size_t)head * DHH * NN + n0 + ty * 4;
#pragma unroll
    for (int jj = 0; jj < 4; jj++) {
        __half2 p0 = __floats2half2_rn(c[0][jj], c[1][jj]);
        __half2 p1 = __floats2half2_rn(c[2][jj], c[3][jj]);
        uint2 u = make_uint2(h2u(p0), h2u(p1));
        *(uint2*)(htb + (size_t)(tx * 4 + jj) * NN) = u;
    }

    const float4 a1v = *(const float4*)(a + head * 2 * DHH + tx * 4);
    const float4 a2v = *(const float4*)(a + head * 2 * DHH + DHH + tx * 4);
#pragma unroll
    for (int ii = 0; ii < 4; ii++) {
        sr1[ty * 4 + ii][tx] = c[ii][0] * a1v.x + c[ii][1] * a1v.y +
                               c[ii][2] * a1v.z + c[ii][3] * a1v.w;
        sr2[ty * 4 + ii][tx] = c[ii][0] * a2v.x + c[ii][1] * a2v.y +
                               c[ii][2] * a2v.z + c[ii][3] * a2v.w;
    }
    __syncthreads();
    if (tid < 32) {
        float s1 = 0.f, s2 = 0.f;
#pragma unroll
        for (int q = 0; q < 16; q++) { s1 += sr1[tid][q]; s2 += sr2[tid][q]; }
        const int idx = head * NN + n0 + tid;
        g_ssrc[idx] = s1;
        g_E[idx] = __expf(s1);
        g_e[idx] = __expf(0.01f * s1);
        g_t_h[idx] = __float2half_rn(s2);
        g_F_h[idx] = __float2half_rn(__expf(s2));
        g_f_h[idx] = __float2half_rn(__expf(0.01f * s2));
    }
}

// ---------------------------------------------------------------------------
// Kernel 3: masked-softmax aggregation via mma.sync fp16 (fp32 accum).
// Register-direct A fragments, ks-OUTER ordering (afr lifetime = 1 k-step
// -> ~8 live fragment regs instead of 32; no spills).
// CTA = 128 i-rows x 1 head x 1024-j slice; 4 warps, each 32i x 64d.
// ---------------------------------------------------------------------------
#define TJ 64
#define JRANGE (NN / NSPLIT)
#define NT (JRANGE / TJ)
#define PITCH 72        // halves; 144B rows -> conflict-free ldmatrix
#define TILE_B 9216     // 64 * PITCH * 2 bytes

__global__ __launch_bounds__(128, 4) void k3_agg() {
    __shared__ __align__(16) __half sB[3][64 * PITCH];    // 27648 B
    __shared__ __align__(16) __half sT[3][192];           // t|F|f per tile

    const int head  = blockIdx.x;
    const int i0    = blockIdx.y * 128;
    const int split = blockIdx.z;
    const int jbase = split * JRANGE;
    const int tid   = threadIdx.x;
    const int lane  = tid & 31;
    const int w     = tid >> 5;
    const int r     = lane >> 2;      // 0..7
    const int cq    = lane & 3;       // 0..3

    // 4 rows per thread: [mi*2+h] = w*32 + mi*16 + r + h*8
    int rowid[4];
    rowid[0] = w * 32 + r;
    rowid[1] = w * 32 + r + 8;
    rowid[2] = w * 32 + 16 + r;
    rowid[3] = w * 32 + 24 + r;

    uint32_t nsi[4], Ei[4], ei[4];
#pragma unroll
    for (int q = 0; q < 4; q++) {
        const int rg = head * NN + i0 + rowid[q];
        nsi[q] = h2u(__float2half2_rn(-g_ssrc[rg]));
        Ei[q]  = h2u(__float2half2_rn(g_E[rg]));
        ei[q]  = h2u(__float2half2_rn(g_e[rg]));
    }
    const uint32_t cap2 = h2u(__float2half2_rn(60000.f));

    const unsigned* madj = g_adjm + (jbase >> 5);
    const __half* hTh = g_hTh + (size_t)head * DHH * NN;

    const __half* tabsrc = nullptr;
    if (tid < 24) {
        const int tab = tid >> 3;
        const __half* base = tab == 0 ? g_t_h : (tab == 1 ? g_F_h : g_f_h);
        tabsrc = base + head * NN + jbase + (tid & 7) * 8;
    }

    const uint32_t sBu = smem_u32(sB);
    const uint32_t sTu = smem_u32(sT);
    const uint32_t lrow = lane & 15;
    const uint32_t lcol = (lane >> 4) * 8;
    const uint32_t bBase = sBu + (lrow * PITCH + lcol) * 2;

    float c[16][4] = {};     // [mi*8 + nt][4]
    float rs[4] = {};

    // ---- preload tile 0 ----
#pragma unroll
    for (int k = 0; k < 4; k++) {
        int ch = tid + k * 128;
        int row = ch >> 3;
        int kc  = ch & 7;
        CP_ASYNC16(sBu + row * 144 + kc * 16,
                   hTh + (size_t)row * NN + jbase + kc * 8);
    }
    if (tid < 24) CP_ASYNC16(sTu + tid * 16, tabsrc);
    CP_COMMIT();

    int bcur = 0;
    for (int t = 0; t < NT; t++) {
        const int bnext = (bcur == 2) ? 0 : bcur + 1;

        // ---- prefetch tile t+1 ----
        if (t + 1 < NT) {
            const int j1 = jbase + (t + 1) * TJ;
            const uint32_t bb = sBu + bnext * TILE_B;
#pragma unroll
            for (int k = 0; k < 4; k++) {
                int ch = tid + k * 128;
                int row = ch >> 3;
                int kc  = ch & 7;
                CP_ASYNC16(bb + row * 144 + kc * 16,
                           hTh + (size_t)row * NN + j1 + kc * 8);
            }
            if (tid < 24)
                CP_ASYNC16(sTu + bnext * 384 + tid * 16, tabsrc + (t + 1) * TJ);
        }
        CP_COMMIT();

        // mask words for this tile: 4 rows x uint2 (64 bits)
        uint2 mw[4];
#pragma unroll
        for (int q = 0; q < 4; q++)
            mw[q] = *(const uint2*)(madj + (size_t)(i0 + rowid[q]) * NW + t * 2);

        CP_WAIT1();
        __syncthreads();     // tile t data (sB[bcur], sT[bcur]) visible

        const __half* Tt = sT[bcur];
        const uint32_t bB = bBase + bcur * TILE_B;

        // ---- ks-OUTER: compute 8 afr regs, consume immediately ----
#pragma unroll
        for (int ks = 0; ks < 4; ks++) {
            const int j0 = ks * 16 + cq * 2;
            const uint32_t t0 = *(const uint32_t*)&Tt[j0];
            const uint32_t t8 = *(const uint32_t*)&Tt[j0 + 8];
            const uint32_t F0 = *(const uint32_t*)&Tt[64 + j0];
            const uint32_t F8 = *(const uint32_t*)&Tt[64 + j0 + 8];
            const uint32_t f0 = *(const uint32_t*)&Tt[128 + j0];
            const uint32_t f8 = *(const uint32_t*)&Tt[128 + j0 + 8];
            const int sh = cq * 2 + (ks & 1) * 16;

            uint32_t afr[2][4];      // [mi][a0..a3] for THIS ks only
#pragma unroll
            for (int mi = 0; mi < 2; mi++) {
#pragma unroll
                for (int h = 0; h < 2; h++) {
                    const int q = mi * 2 + h;
                    const unsigned word = (ks >= 2) ? mw[q].y : mw[q].x;
                    {
                        __half2 cmp = __hgt2(u2h(t0), u2h(nsi[q]));
                        __half2 hiv = __hmul2(u2h(Ei[q]), u2h(F0));
                        __half2 lov = __hmul2(u2h(ei[q]), u2h(f0));
                        __half2 v = __hfma2(cmp, __hsub2(hiv, lov), lov);
                        v = __hmin2(v, u2h(cap2));
                        unsigned bb2 = (word >> sh) & 3u;
                        unsigned mm = ((bb2 & 1u) * 0x3C00u) |
                                      ((bb2 >> 1) * 0x3C000000u);
                        v = __hmul2(v, u2h(mm));
                        float2 vf = __half22float2(v);
                        rs[q] += vf.x + vf.y;
                        afr[mi][h] = h2u(v);
                    }
                    {
                        __half2 cmp = __hgt2(u2h(t8), u2h(nsi[q]));
                        __half2 hiv = __hmul2(u2h(Ei[q]), u2h(F8));
                        __half2 lov = __hmul2(u2h(ei[q]), u2h(f8));
                        __half2 v = __hfma2(cmp, __hsub2(hiv, lov), lov);
                        v = __hmin2(v, u2h(cap2));
                        unsigned bb2 = (word >> (sh + 8)) & 3u;
                        unsigned mm = ((bb2 & 1u) * 0x3C00u) |
                                      ((bb2 >> 1) * 0x3C000000u);
                        v = __hmul2(v, u2h(mm));
                        float2 vf = __half22float2(v);
                        rs[q] += vf.x + vf.y;
                        afr[mi][2 + h] = h2u(v);
                    }
                }
            }

            // consume afr: 4 B-fragment loads + 8 MMAs for this ks
#pragma unroll
            for (int q2 = 0; q2 < 4; q2++) {
                uint32_t b0, b1, b2, b3;
                LDSM4(b0, b1, b2, b3, bB + q2 * (16 * PITCH * 2) + ks * 32);
#pragma unroll
                for (int mi = 0; mi < 2; mi++) {
                    MMA_F16(c[mi * 8 + q2 * 2 + 0],
                            afr[mi][0], afr[mi][1], afr[mi][2], afr[mi][3],
                            b0, b2);
                    MMA_F16(c[mi * 8 + q2 * 2 + 1],
                            afr[mi][0], afr[mi][1], afr[mi][2], afr[mi][3],
                            b1, b3);
                }
            }
        }
        bcur = bnext;
    }

    // ---- rowsums: reduce over the 4 lanes (cq) sharing each row ----
#pragma unroll
    for (int q = 0; q < 4; q++) {
        rs[q] += __shfl_xor_sync(0xffffffffu, rs[q], 1);
        rs[q] += __shfl_xor_sync(0xffffffffu, rs[q], 2);
    }
    if (cq == 0) {
        float* rb = g_rsp + ((size_t)split * NH + head) * NN + i0;
#pragma unroll
        for (int q = 0; q < 4; q++) rb[rowid[q]] = rs[q];
    }

    // ---- write unnormalized acc partials ----
    float* accb = g_acc + (((size_t)split * NH + head) * NN + i0) * DHH;
#pragma unroll
    for (int mi = 0; mi < 2; mi++) {
        const int row0 = rowid[mi * 2];
        const int row1 = rowid[mi * 2 + 1];
#pragma unroll
        for (int nt = 0; nt < 8; nt++) {
            const float* cf = c[mi * 8 + nt];
            const int col = nt * 8 + cq * 2;
            *(float2*)(accb + (size_t)row0 * DHH + col) =
                make_float2(cf[0], cf[1]);
            *(float2*)(accb + (size_t)row1 * DHH + col) =
                make_float2(cf[2], cf[3]);
        }
    }
}

// ---------------------------------------------------------------------------
// Kernel 4: combine 4 split partials, normalize, ELU, store (vectorized).
// ---------------------------------------------------------------------------
__global__ __launch_bounds__(256) void k4_fin(float* __restrict__ out) {
    const int g    = blockIdx.x * 256 + threadIdx.x;   // float4 index
    const int n    = g >> 6;
    const int rem  = g & 63;
    const int head = rem >> 4;
    const int d4   = rem & 15;

    float4 acc = make_float4(0.f, 0.f, 0.f, 0.f);
    float r = 0.f;
#pragma unroll
    for (int s = 0; s < NSPLIT; s++) {
        const float4 v = *(const float4*)(g_acc +
            (((size_t)s * NH + head) * NN + n) * DHH + d4 * 4);
        acc.x += v.x; acc.y += v.y; acc.z += v.z; acc.w += v.w;
        r += g_rsp[((size_t)s * NH + head) * NN + n];
    }
    const float inv = 1.0f / r;
    float z0 = acc.x * inv, z1 = acc.y * inv, z2 = acc.z * inv, z3 = acc.w * inv;
    z0 = z0 > 0.f ? z0 : expm1f(z0);
    z1 = z1 > 0.f ? z1 : expm1f(z1);
    z2 = z2 > 0.f ? z2 : expm1f(z2);
    z3 = z3 > 0.f ? z3 : expm1f(z3);
    *(float4*)(out + (size_t)g * 4) = make_float4(z0, z1, z2, z3);
}

// ---------------------------------------------------------------------------
extern "C" void kernel_launch(void* const* d_in, const int* in_sizes, int n_in,
                              void* d_out, int out_size) {
    (void)in_sizes; (void)n_in; (void)out_size;
    const float* x   = (const float*)d_in[0];
    const int*   adj = (const int*)d_in[1];
    const float* W   = (const float*)d_in[2];
    const float* a   = (const float*)d_in[3];
    float* out = (float*)d_out;

    k0_pack <<<NN * NW / (8 * 8), 256>>>(adj);
    k1_fused<<<dim3(NH, NN / 32), 128>>>(x, W, a);
    k3_agg  <<<dim3(NH, NN / 128, NSPLIT), 128>>>();
    k4_fin  <<<NN * NH * DHH / 1024, 256>>>(out);
}

// round 17
// speedup vs baseline: 1.0948x; 1.0458x over previous
#include <cuda_runtime.h>
#include <cuda_fp16.h>
#include <cstdint>

#define NN   4096
#define FIN  256
#define NH   4
#define DHH  64
#define NW   (NN / 32)      // 128 adj-mask words per row
#define NSPLIT 4

// ------------------------- device globals (no alloc allowed) ---------------
__device__ __half g_hTh[NH * DHH * NN];   // hT[head][d][n] fp16
__device__ float  g_ssrc[NH * NN];
__device__ float  g_E[NH * NN];           // exp(s_src)
__device__ float  g_e[NH * NN];           // exp(0.01*s_src)
__device__ __half g_t_h[NH * NN];         // s_dst (half)
__device__ __half g_F_h[NH * NN];         // exp(s_dst)
__device__ __half g_f_h[NH * NN];         // exp(0.01*s_dst)
__device__ unsigned g_adjm[NN * NW];      // adjacency bitmask
__device__ float  g_acc[NSPLIT * NH * NN * DHH];  // unnormalized partials
__device__ float  g_rsp[NSPLIT * NH * NN];        // rowsum partials
__device__ float  g_wa1[NH * FIN];        // W @ a1 (exact fp32 score path)
__device__ float  g_wa2[NH * FIN];        // W @ a2

// ------------------------- helpers -----------------------------------------
__device__ __forceinline__ uint32_t smem_u32(const void* p) {
    uint32_t a;
    asm("{ .reg .u64 t; cvta.to.shared.u64 t, %1; cvt.u32.u64 %0, t; }"
        : "=r"(a) : "l"(p));
    return a;
}
__device__ __forceinline__ __half2 u2h(uint32_t u) {
    union { uint32_t u; __half2 h; } c; c.u = u; return c.h;
}
__device__ __forceinline__ uint32_t h2u(__half2 h) {
    union { uint32_t u; __half2 h; } c; c.h = h; return c.u;
}
#define LDSM4(r0, r1, r2, r3, addr) \
    asm volatile("ldmatrix.sync.aligned.m8n8.x4.shared.b16 {%0,%1,%2,%3}, [%4];" \
                 : "=r"(r0), "=r"(r1), "=r"(r2), "=r"(r3) : "r"(addr))
#define MMA_F16(c, a0, a1, a2, a3, b0, b1) \
    asm volatile("mma.sync.aligned.m16n8k16.row.col.f32.f16.f16.f32 " \
                 "{%0,%1,%2,%3}, {%4,%5,%6,%7}, {%8,%9}, {%0,%1,%2,%3};" \
                 : "+f"((c)[0]), "+f"((c)[1]), "+f"((c)[2]), "+f"((c)[3]) \
                 : "r"(a0), "r"(a1), "r"(a2), "r"(a3), "r"(b0), "r"(b1))
#define CP_ASYNC16(dst, src) \
    asm volatile("cp.async.cg.shared.global [%0], [%1], 16;" \
                 :: "r"(dst), "l"(src) : "memory")
#define CP_COMMIT() asm volatile("cp.async.commit_group;" ::: "memory")
#define CP_WAIT1()  asm volatile("cp.async.wait_group 1;" ::: "memory")

// ---------------------------------------------------------------------------
// Kernel 0: pack adj into bitmask words (ballot, coalesced).
// Blocks 0..3 additionally compute wa1/wa2 = W @ a1|a2 (tiny, per head).
// ---------------------------------------------------------------------------
__global__ __launch_bounds__(256) void k0_pack(const int* __restrict__ adj,
                                               const float* __restrict__ W,
                                               const float* __restrict__ a) {
    const int warp_g = (blockIdx.x * 256 + threadIdx.x) >> 5;
    const int lane   = threadIdx.x & 31;
    const int* p = adj + (size_t)warp_g * 256 + lane;
    int v[8];
#pragma unroll
    for (int q = 0; q < 8; q++) v[q] = p[q * 32];
#pragma unroll
    for (int q = 0; q < 8; q++) {
        unsigned b = __ballot_sync(0xffffffffu, v[q] != 0);
        if (lane == 0) g_adjm[warp_g * 8 + q] = b;
    }
    // wa vectors: block h computes head h (256 threads = 1 per f)
    if (blockIdx.x < NH) {
        const int head = blockIdx.x;
        const int f = threadIdx.x;
        const float* Wf = W + ((size_t)head * FIN + f) * DHH;
        const float* av = a + head * 2 * DHH;
        float s1 = 0.f, s2 = 0.f;
#pragma unroll 8
        for (int d = 0; d < DHH; d++) {
            float wv = Wf[d];
            s1 += wv * av[d];
            s2 += wv * av[DHH + d];
        }
        g_wa1[head * FIN + f] = s1;
        g_wa2[head * FIN + f] = s2;
    }
}

// ---------------------------------------------------------------------------
// Kernel 1: h = x @ W via mma.sync fp16 (fp32 accum) + exact-fp32 scores.
// CTA = 1 head x 64 n-rows (full d=64); 128 threads = 4 warps x (16n x 64d).
// s1/s2 computed as x . wa in fp32 during the x-tile load (errors in the
// score path do NOT cancel in softmax, so they stay fp32-exact).
// ---------------------------------------------------------------------------
#define K1P 72    // half pitch, 144B rows

__global__ __launch_bounds__(128) void k1_mma(const float* __restrict__ x,
                                              const float* __restrict__ W) {
    __shared__ __align__(16) __half xs[64 * K1P];    // x tile [n][f] fp16
    __shared__ __align__(16) __half ws[64 * K1P];    // W^T tile [d][f] fp16
    __shared__ __align__(16) __half hsm[64 * K1P];   // h^T staging [d][n]
    __shared__ float swa1[FIN], swa2[FIN];
    __shared__ float sS1[64], sS2[64];

    const int head = blockIdx.x;
    const int n0   = blockIdx.y * 64;
    const int tid  = threadIdx.x;
    const int lane = tid & 31;
    const int w    = tid >> 5;
    const int row  = tid >> 1;        // x-load row 0..63
    const int hsel = tid & 1;         // f-half 0..1

    for (int i = tid; i < FIN; i += 128) {
        swa1[i] = g_wa1[head * FIN + i];
        swa2[i] = g_wa2[head * FIN + i];
    }

    const uint32_t xsu = smem_u32(xs);
    const uint32_t wsu = smem_u32(ws);
    const uint32_t aBase = xsu + ((w * 16 + (lane & 15)) * K1P + (lane >> 4) * 8) * 2;
    const uint32_t bBase = wsu + (((lane & 15)) * K1P + (lane >> 4) * 8) * 2;

    float c[8][4] = {};
    float s1p = 0.f, s2p = 0.f;

    for (int kc = 0; kc < 4; kc++) {
        const int f0 = kc * 64;
        __syncthreads();              // xs/ws free (prev chunk's MMA done)

        // ---- x tile: fp32 load -> fp16 smem + fp32 s partials ----
        const float* xrow = x + (size_t)(n0 + row) * FIN + f0 + hsel * 32;
#pragma unroll
        for (int q = 0; q < 8; q++) {
            float4 v = *(const float4*)(xrow + q * 4);
            const int col = hsel * 32 + q * 4;
            const float* w1 = swa1 + f0 + col;
            const float* w2 = swa2 + f0 + col;
            s1p += v.x * w1[0] + v.y * w1[1] + v.z * w1[2] + v.w * w1[3];
            s2p += v.x * w2[0] + v.y * w2[1] + v.z * w2[2] + v.w * w2[3];
            __half2 h0 = __floats2half2_rn(v.x, v.y);
            __half2 h1 = __floats2half2_rn(v.z, v.w);
            *(uint2*)((char*)xs + row * 144 + col * 2) =
                make_uint2(h2u(h0), h2u(h1));
        }
        // ---- W tile: fp32 load -> transposed fp16 smem [d][f] ----
#pragma unroll
        for (int r2 = 0; r2 < 8; r2++) {
            int idx = tid + r2 * 128;     // 1024 float4 slots
            int fr = idx >> 4;            // f 0..63
            int c4 = idx & 15;            // d quad
            float4 v = *(const float4*)(W + ((size_t)head * FIN + f0 + fr) * DHH
                                        + c4 * 4);
            __half* wp = ws + (c4 * 4) * K1P + fr;
            wp[0]        = __float2half_rn(v.x);
            wp[K1P]      = __float2half_rn(v.y);
            wp[2 * K1P]  = __float2half_rn(v.z);
            wp[3 * K1P]  = __float2half_rn(v.w);
        }
        __syncthreads();

        // ---- MMA: 4 ks x 4 q2 (same fragment layout as k3) ----
#pragma unroll
        for (int ks = 0; ks < 4; ks++) {
            uint32_t a0, a1, a2, a3;
            LDSM4(a0, a1, a2, a3, aBase + ks * 32);
#pragma unroll
            for (int q2 = 0; q2 < 4; q2++) {
                uint32_t b0, b1, b2, b3;
                LDSM4(b0, b1, b2, b3, bBase + q2 * (16 * K1P * 2) + ks * 32);
                MMA_F16(c[q2 * 2 + 0], a0, a1, a2, a3, b0, b2);
                MMA_F16(c[q2 * 2 + 1], a0, a1, a2, a3, b1, b3);
            }
        }
    }

    // ---- s reduce (pair over the two f-halves of each row) ----
    s1p += __shfl_xor_sync(0xffffffffu, s1p, 1);
    s2p += __shfl_xor_sync(0xffffffffu, s2p, 1);
    if (!hsel) { sS1[row] = s1p; sS2[row] = s2p; }

    // ---- stage h^T [d][n] in smem from fragments ----
    const int rr = lane >> 2;
    const int cq = lane & 3;
#pragma unroll
    for (int q2 = 0; q2 < 4; q2++) {
#pragma unroll
        for (int hh = 0; hh < 2; hh++) {
            const float* cf = c[q2 * 2 + hh];
            const int d0 = q2 * 16 + hh * 8 + cq * 2;
            const int nA = w * 16 + rr;
            const int nB = nA + 8;
            hsm[d0 * K1P + nA]       = __float2half_rn(cf[0]);
            hsm[(d0 + 1) * K1P + nA] = __float2half_rn(cf[1]);
            hsm[d0 * K1P + nB]       = __float2half_rn(cf[2]);
            hsm[(d0 + 1) * K1P + nB] = __float2half_rn(cf[3]);
        }
    }
    __syncthreads();

    // ---- tables (exact fp32 s) ----
    if (tid < 64) {
        const float s1 = sS1[tid];
        const float s2 = sS2[tid];
        const int idx = head * NN + n0 + tid;
        g_ssrc[idx] = s1;
        g_E[idx] = __expf(s1);
        g_e[idx] = __expf(0.01f * s1);
        g_t_h[idx] = __float2half_rn(s2);
        g_F_h[idx] = __float2half_rn(__expf(s2));
        g_f_h[idx] = __float2half_rn(__expf(0.01f * s2));
    }

    // ---- coalesced h^T store: 64 d-rows x 64 halves ----
#pragma unroll
    for (int q = 0; q < 4; q++) {
        int idx = tid + q * 128;      // 0..511 uint4 slots
        int d = idx >> 3;
        int c8 = idx & 7;
        uint4 v = *(const uint4*)(hsm + d * K1P + c8 * 8);
        *(uint4*)(g_hTh + (size_t)head * DHH * NN + (size_t)d * NN + n0 + c8 * 8) = v;
    }
}

// ---------------------------------------------------------------------------
// Kernel 3: masked-softmax aggregation via mma.sync fp16 (fp32 accum).
// Register-direct A fragments, ks-outer. UNCHANGED (proven, round 16).
// ---------------------------------------------------------------------------
#define TJ 64
#define JRANGE (NN / NSPLIT)
#define NT (JRANGE / TJ)
#define PITCH 72
#define TILE_B 9216

__global__ __launch_bounds__(128, 4) void k3_agg() {
    __shared__ __align__(16) __half sB[3][64 * PITCH];
    __shared__ __align__(16) __half sT[3][192];

    const int head  = blockIdx.x;
    const int i0    = blockIdx.y * 128;
    const int split = blockIdx.z;
    const int jbase = split * JRANGE;
    const int tid   = threadIdx.x;
    const int lane  = tid & 31;
    const int w     = tid >> 5;
    const int r     = lane >> 2;
    const int cq    = lane & 3;

    int rowid[4];
    rowid[0] = w * 32 + r;
    rowid[1] = w * 32 + r + 8;
    rowid[2] = w * 32 + 16 + r;
    rowid[3] = w * 32 + 24 + r;

    uint32_t nsi[4], Ei[4], ei[4];
#pragma unroll
    for (int q = 0; q < 4; q++) {
        const int rg = head * NN + i0 + rowid[q];
        nsi[q] = h2u(__float2half2_rn(-g_ssrc[rg]));
        Ei[q]  = h2u(__float2half2_rn(g_E[rg]));
        ei[q]  = h2u(__float2half2_rn(g_e[rg]));
    }
    const uint32_t cap2 = h2u(__float2half2_rn(60000.f));

    const unsigned* madj = g_adjm + (jbase >> 5);
    const __half* hTh = g_hTh + (size_t)head * DHH * NN;

    const __half* tabsrc = nullptr;
    if (tid < 24) {
        const int tab = tid >> 3;
        const __half* base = tab == 0 ? g_t_h : (tab == 1 ? g_F_h : g_f_h);
        tabsrc = base + head * NN + jbase + (tid & 7) * 8;
    }

    const uint32_t sBu = smem_u32(sB);
    const uint32_t sTu = smem_u32(sT);
    const uint32_t lrow = lane & 15;
    const uint32_t lcol = (lane >> 4) * 8;
    const uint32_t bBase = sBu + (lrow * PITCH + lcol) * 2;

    float c[16][4] = {};
    float rs[4] = {};

#pragma unroll
    for (int k = 0; k < 4; k++) {
        int ch = tid + k * 128;
        int row = ch >> 3;
        int kc  = ch & 7;
        CP_ASYNC16(sBu + row * 144 + kc * 16,
                   hTh + (size_t)row * NN + jbase + kc * 8);
    }
    if (tid < 24) CP_ASYNC16(sTu + tid * 16, tabsrc);
    CP_COMMIT();

    int bcur = 0;
    for (int t = 0; t < NT; t++) {
        const int bnext = (bcur == 2) ? 0 : bcur + 1;

        if (t + 1 < NT) {
            const int j1 = jbase + (t + 1) * TJ;
            const uint32_t bb = sBu + bnext * TILE_B;
#pragma unroll
            for (int k = 0; k < 4; k++) {
                int ch = tid + k * 128;
                int row = ch >> 3;
                int kc  = ch & 7;
                CP_ASYNC16(bb + row * 144 + kc * 16,
                           hTh + (size_t)row * NN + j1 + kc * 8);
            }
            if (tid < 24)
                CP_ASYNC16(sTu + bnext * 384 + tid * 16, tabsrc + (t + 1) * TJ);
        }
        CP_COMMIT();

        uint2 mw[4];
#pragma unroll
        for (int q = 0; q < 4; q++)
            mw[q] = *(const uint2*)(madj + (size_t)(i0 + rowid[q]) * NW + t * 2);

        CP_WAIT1();
        __syncthreads();

        const __half* Tt = sT[bcur];
        const uint32_t bB = bBase + bcur * TILE_B;

#pragma unroll
        for (int ks = 0; ks < 4; ks++) {
            const int j0 = ks * 16 + cq * 2;
            const uint32_t t0 = *(const uint32_t*)&Tt[j0];
            const uint32_t t8 = *(const uint32_t*)&Tt[j0 + 8];
            const uint32_t F0 = *(const uint32_t*)&Tt[64 + j0];
            const uint32_t F8 = *(const uint32_t*)&Tt[64 + j0 + 8];
            const uint32_t f0 = *(const uint32_t*)&Tt[128 + j0];
            const uint32_t f8 = *(const uint32_t*)&Tt[128 + j0 + 8];
            const int sh = cq * 2 + (ks & 1) * 16;

            uint32_t afr[2][4];
#pragma unroll
            for (int mi = 0; mi < 2; mi++) {
#pragma unroll
                for (int h = 0; h < 2; h++) {
                    const int q = mi * 2 + h;
                    const unsigned word = (ks >= 2) ? mw[q].y : mw[q].x;
                    {
                        __half2 cmp = __hgt2(u2h(t0), u2h(nsi[q]));
                        __half2 hiv = __hmul2(u2h(Ei[q]), u2h(F0));
                        __half2 lov = __hmul2(u2h(ei[q]), u2h(f0));
                        __half2 v = __hfma2(cmp, __hsub2(hiv, lov), lov);
                        v = __hmin2(v, u2h(cap2));
                        unsigned bb2 = (word >> sh) & 3u;
                        unsigned mm = ((bb2 & 1u) * 0x3C00u) |
                                      ((bb2 >> 1) * 0x3C000000u);
                        v = __hmul2(v, u2h(mm));
                        float2 vf = __half22float2(v);
                        rs[q] += vf.x + vf.y;
                        afr[mi][h] = h2u(v);
                    }
                    {
                        __half2 cmp = __hgt2(u2h(t8), u2h(nsi[q]));
                        __half2 hiv = __hmul2(u2h(Ei[q]), u2h(F8));
                        __half2 lov = __hmul2(u2h(ei[q]), u2h(f8));
                        __half2 v = __hfma2(cmp, __hsub2(hiv, lov), lov);
                        v = __hmin2(v, u2h(cap2));
                        unsigned bb2 = (word >> (sh + 8)) & 3u;
                        unsigned mm = ((bb2 & 1u) * 0x3C00u) |
                                      ((bb2 >> 1) * 0x3C000000u);
                        v = __hmul2(v, u2h(mm));
                        float2 vf = __half22float2(v);
                        rs[q] += vf.x + vf.y;
                        afr[mi][2 + h] = h2u(v);
                    }
                }
            }

#pragma unroll
            for (int q2 = 0; q2 < 4; q2++) {
                uint32_t b0, b1, b2, b3;
                LDSM4(b0, b1, b2, b3, bB + q2 * (16 * PITCH * 2) + ks * 32);
#pragma unroll
                for (int mi = 0; mi < 2; mi++) {
                    MMA_F16(c[mi * 8 + q2 * 2 + 0],
                            afr[mi][0], afr[mi][1], afr[mi][2], afr[mi][3],
                            b0, b2);
                    MMA_F16(c[mi * 8 + q2 * 2 + 1],
                            afr[mi][0], afr[mi][1], afr[mi][2], afr[mi][3],
                            b1, b3);
                }
            }
        }
        bcur = bnext;
    }

#pragma unroll
    for (int q = 0; q < 4; q++) {
        rs[q] += __shfl_xor_sync(0xffffffffu, rs[q], 1);
        rs[q] += __shfl_xor_sync(0xffffffffu, rs[q], 2);
    }
    if (cq == 0) {
        float* rb = g_rsp + ((size_t)split * NH + head) * NN + i0;
#pragma unroll
        for (int q = 0; q < 4; q++) rb[rowid[q]] = rs[q];
    }

    float* accb = g_acc + (((size_t)split * NH + head) * NN + i0) * DHH;
#pragma unroll
    for (int mi = 0; mi < 2; mi++) {
        const int row0 = rowid[mi * 2];
        const int row1 = rowid[mi * 2 + 1];
#pragma unroll
        for (int nt = 0; nt < 8; nt++) {
            const float* cf = c[mi * 8 + nt];
            const int col = nt * 8 + cq * 2;
            *(float2*)(accb + (size_t)row0 * DHH + col) =
                make_float2(cf[0], cf[1]);
            *(float2*)(accb + (size_t)row1 * DHH + col) =
                make_float2(cf[2], cf[3]);
        }
    }
}

// ---------------------------------------------------------------------------
// Kernel 4: combine 4 split partials, normalize, ELU, store (vectorized).
// ---------------------------------------------------------------------------
__global__ __launch_bounds__(256) void k4_fin(float* __restrict__ out) {
    const int g    = blockIdx.x * 256 + threadIdx.x;
    const int n    = g >> 6;
    const int rem  = g & 63;
    const int head = rem >> 4;
    const int d4   = rem & 15;

    float4 acc = make_float4(0.f, 0.f, 0.f, 0.f);
    float r = 0.f;
#pragma unroll
    for (int s = 0; s < NSPLIT; s++) {
        const float4 v = *(const float4*)(g_acc +
            (((size_t)s * NH + head) * NN + n) * DHH + d4 * 4);
        acc.x += v.x; acc.y += v.y; acc.z += v.z; acc.w += v.w;
        r += g_rsp[((size_t)s * NH + head) * NN + n];
    }
    const float inv = 1.0f / r;
    float z0 = acc.x * inv, z1 = acc.y * inv, z2 = acc.z * inv, z3 = acc.w * inv;
    z0 = z0 > 0.f ? z0 : expm1f(z0);
    z1 = z1 > 0.f ? z1 : expm1f(z1);
    z2 = z2 > 0.f ? z2 : expm1f(z2);
    z3 = z3 > 0.f ? z3 : expm1f(z3);
    *(float4*)(out + (size_t)g * 4) = make_float4(z0, z1, z2, z3);
}

// ---------------------------------------------------------------------------
extern "C" void kernel_launch(void* const* d_in, const int* in_sizes, int n_in,
                              void* d_out, int out_size) {
    (void)in_sizes; (void)n_in; (void)out_size;
    const float* x   = (const float*)d_in[0];
    const int*   adj = (const int*)d_in[1];
    const float* W   = (const float*)d_in[2];
    const float* a   = (const float*)d_in[3];
    float* out = (float*)d_out;

    k0_pack<<<NN * NW / (8 * 8), 256>>>(adj, W, a);
    k1_mma <<<dim3(NH, NN / 64), 128>>>(x, W);
    k3_agg <<<dim3(NH, NN / 128, NSPLIT), 128>>>();
    k4_fin <<<NN * NH * DHH / 1024, 256>>>(out);
}